// round 1
// baseline (speedup 1.0000x reference)
#include <cuda_runtime.h>
#include <cstdint>

#define STATE   24
#define L1D     100
#define L2D     100
#define ACT     6
#define NCHOL   21
#define NHEAD   27   // 6 mean + 21 chol
#define TPB     128

typedef unsigned long long ull;

// ---- f32x2 packed helpers (SASS FFMA2 path; ptxas never emits it from C++) ----
__device__ __forceinline__ ull pack2(float a, float b) {
    ull r; asm("mov.b64 %0,{%1,%2};" : "=l"(r) : "f"(a), "f"(b)); return r;
}
__device__ __forceinline__ void unpack2(ull v, float& a, float& b) {
    asm("mov.b64 {%0,%1},%2;" : "=f"(a), "=f"(b) : "l"(v));
}
__device__ __forceinline__ ull ffma2(ull a, ull b, ull c) {
    ull d; asm("fma.rn.f32x2 %0,%1,%2,%3;" : "=l"(d) : "l"(a), "l"(b), "l"(c)); return d;
}

// tril_indices(6) order: (0,0),(1,0),(1,1),(2,0),...
__constant__ int c_row[NCHOL] = {0,1,1,2,2,2,3,3,3,3,4,4,4,4,4,5,5,5,5,5,5};
__constant__ int c_col[NCHOL] = {0,0,1,0,1,2,0,1,2,3,0,1,2,3,4,0,1,2,3,4,5};

// Shared memory layout (floats):
//   s_w1  [100*24]  @ 0       (row-major, i-pairs contiguous -> b64 reads)
//   s_b1  [100]     @ 2400
//   s_b2  [100]     @ 2500    (j-pairs contiguous -> b64 init of acc)
//   s_bh  [28]      @ 2600
//   s_w2t [100*100] @ 2628    (TRANSPOSED: [k][j], j-pairs contiguous)
//   s_wh  [27*100]  @ 12628   (Wm rows then Wc rows, j-pairs contiguous)
#define SMEM_FLOATS 15328

extern __shared__ float smem[];

__global__ void __launch_bounds__(TPB, 3)
actor_kernel(const float* __restrict__ states,
             const float* __restrict__ W1, const float* __restrict__ b1,
             const float* __restrict__ W2, const float* __restrict__ b2,
             const float* __restrict__ Wm, const float* __restrict__ bm,
             const float* __restrict__ Wc, const float* __restrict__ bc,
             float* __restrict__ out, int B)
{
    float* s_w1  = smem;
    float* s_b1  = smem + 2400;
    float* s_b2  = smem + 2500;
    float* s_bh  = smem + 2600;
    float* s_w2t = smem + 2628;
    float* s_wh  = smem + 12628;

    const int tid = threadIdx.x;

    // ---- cooperative weight staging ----
    for (int i = tid; i < L1D * STATE; i += TPB) s_w1[i] = W1[i];
    for (int i = tid; i < L1D; i += TPB) { s_b1[i] = b1[i]; s_b2[i] = b2[i]; }
    if (tid < NHEAD) s_bh[tid] = (tid < ACT) ? bm[tid] : bc[tid - ACT];
    for (int i = tid; i < L2D * L1D; i += TPB) {
        int j = i / L1D, k = i - j * L1D;          // read W2 coalesced [j][k]
        s_w2t[k * L2D + j] = W2[i];                // store transposed [k][j]
    }
    for (int i = tid; i < NHEAD * L2D; i += TPB)
        s_wh[i] = (i < ACT * L2D) ? Wm[i] : Wc[i - ACT * L2D];
    __syncthreads();

    const int b = blockIdx.x * TPB + tid;
    if (b >= B) return;

    // ---- load state row as 12 packed pairs (rows are 96B => 16B aligned) ----
    ull sp[STATE / 2];
    const float4* srow = reinterpret_cast<const float4*>(states + (size_t)b * STATE);
    #pragma unroll
    for (int q = 0; q < 6; q++) {
        float4 t = srow[q];
        sp[2 * q]     = pack2(t.x, t.y);
        sp[2 * q + 1] = pack2(t.z, t.w);
    }

    // ---- acc2 = b2 (50 packed pairs) ----
    ull acc[L2D / 2];
    const ull* b2p = reinterpret_cast<const ull*>(s_b2);
    #pragma unroll
    for (int jp = 0; jp < 50; jp++) acc[jp] = b2p[jp];

    // ---- fused GEMM1 (produce x1[k]) + rank-1 update of acc2 ----
    #pragma unroll 1
    for (int k = 0; k < L1D; k++) {
        // x1[k] = relu(b1[k] + dot(W1[k,:], s)) via packed partials
        const ulonglong2* w1r = reinterpret_cast<const ulonglong2*>(s_w1 + k * STATE);
        ull a0 = 0ULL, a1 = 0ULL;   // bit pattern 0 == (0.0f, 0.0f)
        #pragma unroll
        for (int q = 0; q < 6; q++) {
            ulonglong2 w = w1r[q];
            a0 = ffma2(w.x, sp[2 * q],     a0);
            a1 = ffma2(w.y, sp[2 * q + 1], a1);
        }
        float u0, u1, u2, u3;
        unpack2(a0, u0, u1); unpack2(a1, u2, u3);
        float x = u0 + u1 + u2 + u3 + s_b1[k];
        x = fmaxf(x, 0.0f);
        ull xd = pack2(x, x);

        // acc2[j] += W2[j,k] * x for all j (packed pairs, LDS.128 broadcast)
        const ulonglong2* w2r = reinterpret_cast<const ulonglong2*>(s_w2t + k * L2D);
        #pragma unroll
        for (int jq = 0; jq < 25; jq++) {
            ulonglong2 w = w2r[jq];
            acc[2 * jq]     = ffma2(w.x, xd, acc[2 * jq]);
            acc[2 * jq + 1] = ffma2(w.y, xd, acc[2 * jq + 1]);
        }
    }

    // ---- ReLU on x2 ----
    #pragma unroll
    for (int jp = 0; jp < 50; jp++) {
        float u, v; unpack2(acc[jp], u, v);
        acc[jp] = pack2(fmaxf(u, 0.0f), fmaxf(v, 0.0f));
    }

    // ---- outputs ----
    float* om = out + (size_t)b * ACT;                       // mean  [B,6]
    float* oc = out + (size_t)B * ACT + (size_t)b * 36;      // chol  [B,6,6]

    // zero full 6x6 (d_out is poisoned), 16B-aligned vector stores
    const float4 z4 = make_float4(0.f, 0.f, 0.f, 0.f);
    #pragma unroll
    for (int q = 0; q < 9; q++) reinterpret_cast<float4*>(oc)[q] = z4;

    // 27 head dots over x2, epilogue per head
    #pragma unroll 1
    for (int o = 0; o < NHEAD; o++) {
        const ulonglong2* whr = reinterpret_cast<const ulonglong2*>(s_wh + o * L2D);
        ull a0 = 0ULL, a1 = 0ULL;
        #pragma unroll
        for (int jq = 0; jq < 25; jq++) {
            ulonglong2 w = whr[jq];
            a0 = ffma2(w.x, acc[2 * jq],     a0);
            a1 = ffma2(w.y, acc[2 * jq + 1], a1);
        }
        float u0, u1, u2, u3;
        unpack2(a0, u0, u1); unpack2(a1, u2, u3);
        float h = u0 + u1 + u2 + u3 + s_bh[o];
        if (o < ACT) {
            om[o] = tanhf(h);
        } else {
            // numerically-stable softplus, matches jax.nn.softplus
            float spv = fmaxf(h, 0.0f) + log1pf(expf(-fabsf(h)));
            int t = o - ACT;
            oc[c_row[t] * 6 + c_col[t]] = spv;
        }
    }
}

extern "C" void kernel_launch(void* const* d_in, const int* in_sizes, int n_in,
                              void* d_out, int out_size)
{
    const float* states = (const float*)d_in[0];
    const float* W1 = (const float*)d_in[1];
    const float* b1 = (const float*)d_in[2];
    const float* W2 = (const float*)d_in[3];
    const float* b2 = (const float*)d_in[4];
    const float* Wm = (const float*)d_in[5];
    const float* bm = (const float*)d_in[6];
    const float* Wc = (const float*)d_in[7];
    const float* bc = (const float*)d_in[8];
    float* out = (float*)d_out;

    const int B = in_sizes[0] / STATE;
    const size_t smem_bytes = SMEM_FLOATS * sizeof(float);   // ~61.3 KB -> needs opt-in

    static bool attr_set = false;
    // cudaFuncSetAttribute is not a stream op; safe & idempotent under capture.
    cudaFuncSetAttribute(actor_kernel,
                         cudaFuncAttributeMaxDynamicSharedMemorySize,
                         (int)smem_bytes);
    (void)attr_set;

    const int blocks = (B + TPB - 1) / TPB;
    actor_kernel<<<blocks, TPB, smem_bytes>>>(states, W1, b1, W2, b2,
                                              Wm, bm, Wc, bc, out, B);
}

// round 3
// speedup vs baseline: 1.4183x; 1.4183x over previous
#include <cuda_runtime.h>
#include <cstdint>

#define TPB     128
#define TILE_M  128
#define STATE   24
#define L1D     100
#define L2D     100
#define NHEAD   27
#define ACT     6

#define KP1     36     // As1 float stride (36 mod 32 = 4 -> conflict-free A frags)
#define KP2     108    // As2 float stride (108 mod 32 = 12 -> conflict-free)
#define NT12    13     // n-tiles (104 cols) for layers 1,2
#define NT3     4      // n-tiles (32 cols) for head layer
#define KS1     4      // k-steps layer1 (K=25 padded to 32)
#define KS23    13     // k-steps layers 2,3 (K=101 padded to 104)

// ---- smem layout (float offsets) ----
#define F_BP1   0
#define F_BP2   (F_BP1 + KS1*NT12*32*4)        //  6656
#define F_BP3   (F_BP2 + KS23*NT12*32*4)       // 28288
#define F_AS1   (F_BP3 + KS23*NT3*32*4)        // 34944  (also chol staging 128*36)
#define F_AS2   (F_AS1 + TILE_M*KP1)           // 39552
#define F_MEAN  (F_AS2 + TILE_M*KP2)           // 53376
#define F_TOTAL (F_MEAN + TILE_M*ACT)          // 54144 floats = 216576 B

// tril scatter: chol-vec q -> flat 6x6 index; plus the 15 always-zero uppers
__constant__ int c_pos[21]   = {0,6,7,12,13,14,18,19,20,21,24,25,26,27,28,30,31,32,33,34,35};
__constant__ int c_upper[15] = {1,2,3,4,5,8,9,10,11,15,16,17,22,23,29};

__device__ __forceinline__ void tf32s(float x, uint32_t& hi, uint32_t& lo) {
    asm("cvt.rna.tf32.f32 %0, %1;" : "=r"(hi) : "f"(x));
    float r = x - __uint_as_float(hi);
    asm("cvt.rna.tf32.f32 %0, %1;" : "=r"(lo) : "f"(r));
}

__device__ __forceinline__ void mma8(float* c, const uint32_t* a, uint32_t b0, uint32_t b1) {
    asm volatile("mma.sync.aligned.m16n8k8.row.col.f32.tf32.tf32.f32 "
                 "{%0,%1,%2,%3},{%4,%5,%6,%7},{%8,%9},{%0,%1,%2,%3};"
                 : "+f"(c[0]), "+f"(c[1]), "+f"(c[2]), "+f"(c[3])
                 : "r"(a[0]), "r"(a[1]), "r"(a[2]), "r"(a[3]), "r"(b0), "r"(b1));
}

extern __shared__ float smem[];

// Generic 3xTF32 warp GEMM: A [128 x K] in smem (stride KP), B packed frags.
// Warp computes rows [wrow, wrow+32) x all N into c[2][NT][4].
template<int KS, int NT, int KP>
__device__ __forceinline__ void wgemm(const float* As, const float4* Bp,
                                      int wrow, int g, int t, int lane,
                                      float c[2][NT][4])
{
    #pragma unroll
    for (int mt = 0; mt < 2; mt++)
        #pragma unroll
        for (int nt = 0; nt < NT; nt++)
            #pragma unroll
            for (int i = 0; i < 4; i++) c[mt][nt][i] = 0.0f;

    const float* r0 = As + (wrow + g) * KP;          // mt0 rows g, g+8
    const float* r1 = As + (wrow + 16 + g) * KP;     // mt1 rows g+16, g+24

    #pragma unroll 1
    for (int ks = 0; ks < KS; ks++) {
        const int col = t + 8 * ks;
        uint32_t ahi[2][4], alo[2][4];
        {
            float a0 = r0[col],          a1 = r0[8 * KP + col];
            float a2 = r0[col + 4],      a3 = r0[8 * KP + col + 4];
            tf32s(a0, ahi[0][0], alo[0][0]); tf32s(a1, ahi[0][1], alo[0][1]);
            tf32s(a2, ahi[0][2], alo[0][2]); tf32s(a3, ahi[0][3], alo[0][3]);
            float b0 = r1[col],          b1v = r1[8 * KP + col];
            float b2 = r1[col + 4],      b3 = r1[8 * KP + col + 4];
            tf32s(b0, ahi[1][0], alo[1][0]); tf32s(b1v, ahi[1][1], alo[1][1]);
            tf32s(b2, ahi[1][2], alo[1][2]); tf32s(b3, ahi[1][3], alo[1][3]);
        }
        const float4* bp = Bp + (ks * NT) * 32 + lane;
        #pragma unroll
        for (int nt = 0; nt < NT; nt++) {
            float4 b = bp[nt * 32];
            uint32_t bh0 = __float_as_uint(b.x), bh1 = __float_as_uint(b.y);
            uint32_t bl0 = __float_as_uint(b.z), bl1 = __float_as_uint(b.w);
            #pragma unroll
            for (int mt = 0; mt < 2; mt++) {
                mma8(c[mt][nt], ahi[mt], bh0, bh1);
                mma8(c[mt][nt], alo[mt], bh0, bh1);
                mma8(c[mt][nt], ahi[mt], bl0, bl1);
            }
        }
    }
}

// relu + store C frags into As2 (cols < 100 only), rows wrow..wrow+31
__device__ __forceinline__ void epi_relu(float c[2][NT12][4], float* As2,
                                         int wrow, int g, int t)
{
    #pragma unroll
    for (int mt = 0; mt < 2; mt++) {
        const int row = wrow + mt * 16 + g;
        #pragma unroll
        for (int nt = 0; nt < NT12; nt++) {
            if (nt == 12 && t >= 2) continue;        // skip cols >= 100
            const int col = 8 * nt + 2 * t;
            float2 v0, v1;
            v0.x = fmaxf(c[mt][nt][0], 0.f); v0.y = fmaxf(c[mt][nt][1], 0.f);
            v1.x = fmaxf(c[mt][nt][2], 0.f); v1.y = fmaxf(c[mt][nt][3], 0.f);
            *reinterpret_cast<float2*>(As2 + row * KP2 + col)       = v0;
            *reinterpret_cast<float2*>(As2 + (row + 8) * KP2 + col) = v1;
        }
    }
}

__global__ void __launch_bounds__(TPB, 1)
actor_mma(const float* __restrict__ states,
          const float* __restrict__ W1, const float* __restrict__ b1,
          const float* __restrict__ W2, const float* __restrict__ b2,
          const float* __restrict__ Wm, const float* __restrict__ bm,
          const float* __restrict__ Wc, const float* __restrict__ bc,
          float* __restrict__ out, int B)
{
    const int tid  = threadIdx.x;
    const int lane = tid & 31;
    const int wid  = tid >> 5;
    const int g    = lane >> 2;
    const int t    = lane & 3;
    const int wrow = wid * 32;

    float* As1   = smem + F_AS1;      // X tile; reused as chol staging
    float* As2   = smem + F_AS2;      // hidden activations
    float* sMean = smem + F_MEAN;
    const float4* Bp1 = reinterpret_cast<const float4*>(smem + F_BP1);
    const float4* Bp2 = reinterpret_cast<const float4*>(smem + F_BP2);
    const float4* Bp3 = reinterpret_cast<const float4*>(smem + F_BP3);

    // ---- stage packed weight fragments (hi/lo tf32 split), biases folded ----
    for (int i = tid; i < KS1 * NT12 * 32; i += TPB) {
        int ln = i & 31, slot = i >> 5, ks = slot / NT12, nt = slot - ks * NT12;
        int gg = ln >> 2, tt = ln & 3, n = gg + 8 * nt, k0 = tt + 8 * ks, k1 = k0 + 4;
        float w0 = (n < L1D) ? (k0 < STATE ? W1[n * STATE + k0] : (k0 == STATE ? b1[n] : 0.f)) : 0.f;
        float w1 = (n < L1D) ? (k1 < STATE ? W1[n * STATE + k1] : (k1 == STATE ? b1[n] : 0.f)) : 0.f;
        uint32_t h0, l0, h1, l1; tf32s(w0, h0, l0); tf32s(w1, h1, l1);
        reinterpret_cast<uint4*>(smem + F_BP1)[i] = make_uint4(h0, h1, l0, l1);
    }
    for (int i = tid; i < KS23 * NT12 * 32; i += TPB) {
        int ln = i & 31, slot = i >> 5, ks = slot / NT12, nt = slot - ks * NT12;
        int gg = ln >> 2, tt = ln & 3, n = gg + 8 * nt, k0 = tt + 8 * ks, k1 = k0 + 4;
        float w0 = (n < L2D) ? (k0 < L1D ? W2[n * L1D + k0] : (k0 == L1D ? b2[n] : 0.f)) : 0.f;
        float w1 = (n < L2D) ? (k1 < L1D ? W2[n * L1D + k1] : (k1 == L1D ? b2[n] : 0.f)) : 0.f;
        uint32_t h0, l0, h1, l1; tf32s(w0, h0, l0); tf32s(w1, h1, l1);
        reinterpret_cast<uint4*>(smem + F_BP2)[i] = make_uint4(h0, h1, l0, l1);
    }
    for (int i = tid; i < KS23 * NT3 * 32; i += TPB) {
        int ln = i & 31, slot = i >> 5, ks = slot / NT3, nt = slot - ks * NT3;
        int gg = ln >> 2, tt = ln & 3, n = gg + 8 * nt, k0 = tt + 8 * ks, k1 = k0 + 4;
        float w0 = 0.f, w1 = 0.f;
        if (n < ACT) {
            w0 = k0 < L2D ? Wm[n * L2D + k0] : (k0 == L2D ? bm[n] : 0.f);
            w1 = k1 < L2D ? Wm[n * L2D + k1] : (k1 == L2D ? bm[n] : 0.f);
        } else if (n < NHEAD) {
            w0 = k0 < L2D ? Wc[(n - ACT) * L2D + k0] : (k0 == L2D ? bc[n - ACT] : 0.f);
            w1 = k1 < L2D ? Wc[(n - ACT) * L2D + k1] : (k1 == L2D ? bc[n - ACT] : 0.f);
        }
        uint32_t h0, l0, h1, l1; tf32s(w0, h0, l0); tf32s(w1, h1, l1);
        reinterpret_cast<uint4*>(smem + F_BP3)[i] = make_uint4(h0, h1, l0, l1);
    }
    // zero As2 (pad cols 101..107 must stay zero; col 100 refreshed per tile)
    for (int i = tid; i < TILE_M * KP2; i += TPB) As2[i] = 0.0f;
    __syncthreads();

    const int ntiles = (B + TILE_M - 1) / TILE_M;

    for (int tile = blockIdx.x; tile < ntiles; tile += gridDim.x) {
        // ---- load X row (thread = row), pad cols 24..35: bias=1 then zeros ----
        {
            long m = (long)tile * TILE_M + tid; if (m >= B) m = B - 1;
            const float4* src = reinterpret_cast<const float4*>(states + m * STATE);
            float4* dst = reinterpret_cast<float4*>(As1 + tid * KP1);
            #pragma unroll
            for (int q = 0; q < 6; q++) dst[q] = src[q];
            dst[6] = make_float4(1.f, 0.f, 0.f, 0.f);
            dst[7] = make_float4(0.f, 0.f, 0.f, 0.f);
            dst[8] = make_float4(0.f, 0.f, 0.f, 0.f);
        }
        __syncthreads();                                   // S1

        // ---- layer 1 ----
        {
            float c1[2][NT12][4];
            wgemm<KS1, NT12, KP1>(As1, Bp1, wrow, g, t, lane, c1);
            epi_relu(c1, As2, wrow, g, t);
            As2[tid * KP2 + 100] = 1.0f;                   // bias column
        }
        __syncthreads();                                   // S2

        // ---- layer 2 ----
        {
            float c2[2][NT12][4];
            wgemm<KS23, NT12, KP2>(As2, Bp2, wrow, g, t, lane, c2);
            __syncthreads();                               // S3: As2 reads done
            epi_relu(c2, As2, wrow, g, t);
            As2[tid * KP2 + 100] = 1.0f;
        }
        __syncthreads();                                   // S4

        // ---- head layer + scatter ----
        {
            float c3[2][NT3][4];
            wgemm<KS23, NT3, KP2>(As2, Bp3, wrow, g, t, lane, c3);
            #pragma unroll
            for (int mt = 0; mt < 2; mt++)
                #pragma unroll
                for (int nt = 0; nt < NT3; nt++)
                    #pragma unroll
                    for (int i = 0; i < 4; i++) {
                        int row = wrow + mt * 16 + g + ((i >= 2) ? 8 : 0);
                        int col = 8 * nt + 2 * t + (i & 1);
                        float v = c3[mt][nt][i];
                        if (col < ACT) {
                            sMean[row * ACT + col] = tanhf(v);
                        } else if (col < NHEAD) {
                            float sp = fmaxf(v, 0.f) + log1pf(expf(-fabsf(v)));
                            As1[row * 36 + c_pos[col - ACT]] = sp;   // chol staging
                        }
                    }
            #pragma unroll
            for (int j = 0; j < 15; j++) As1[tid * 36 + c_upper[j]] = 0.0f;
        }
        __syncthreads();                                   // S5

        // ---- coalesced writeback ----
        if ((tile + 1) * TILE_M <= B) {
            float4* pm = reinterpret_cast<float4*>(out + (size_t)tile * (TILE_M * ACT));
            const float4* sm4 = reinterpret_cast<const float4*>(sMean);
            #pragma unroll
            for (int i = tid; i < TILE_M * ACT / 4; i += TPB) pm[i] = sm4[i];
            float4* pc = reinterpret_cast<float4*>(out + (size_t)B * ACT + (size_t)tile * (TILE_M * 36));
            const float4* sc4 = reinterpret_cast<const float4*>(As1);
            #pragma unroll
            for (int i = tid; i < TILE_M * 36 / 4; i += TPB) pc[i] = sc4[i];
        } else {
            int nrow = B - tile * TILE_M;
            for (int i = tid; i < nrow * ACT; i += TPB)
                out[(size_t)tile * (TILE_M * ACT) + i] = sMean[i];
            for (int i = tid; i < nrow * 36; i += TPB)
                out[(size_t)B * ACT + (size_t)tile * (TILE_M * 36) + i] = As1[i];
        }
        __syncthreads();                                   // S6 (staging reuse)
    }
}

extern "C" void kernel_launch(void* const* d_in, const int* in_sizes, int n_in,
                              void* d_out, int out_size)
{
    const float* states = (const float*)d_in[0];
    const float* W1 = (const float*)d_in[1];
    const float* b1 = (const float*)d_in[2];
    const float* W2 = (const float*)d_in[3];
    const float* b2 = (const float*)d_in[4];
    const float* Wm = (const float*)d_in[5];
    const float* bm = (const float*)d_in[6];
    const float* Wc = (const float*)d_in[7];
    const float* bc = (const float*)d_in[8];
    float* out = (float*)d_out;

    const int B = in_sizes[0] / STATE;
    const int ntiles = (B + TILE_M - 1) / TILE_M;
    const size_t smem_bytes = (size_t)F_TOTAL * sizeof(float);   // ~211.5 KB

    cudaFuncSetAttribute(actor_mma,
                         cudaFuncAttributeMaxDynamicSharedMemorySize,
                         (int)smem_bytes);

    int grid = ntiles < 148 ? ntiles : 148;   // persistent, 1 CTA/SM
    actor_mma<<<grid, TPB, smem_bytes>>>(states, W1, b1, W2, b2,
                                         Wm, bm, Wc, bc, out, B);
}

// round 4
// speedup vs baseline: 1.5786x; 1.1130x over previous
#include <cuda_runtime.h>
#include <cstdint>

#define TPB     256
#define TILE_M  128
#define STATE   24
#define L1D     100
#define L2D     100
#define NHEAD   27
#define ACT     6

#define KP1     36     // As1 stride: (36g+t) mod 32 = 4g+t -> conflict-free
#define KP2     108    // As2 stride: 12g+t pattern -> conflict-free
#define NT12    13     // n-tiles (104 cols) layers 1,2
#define NT3     4      // n-tiles (32 cols) head layer
#define KS1     4      // k-steps layer1 (K=25 pad 32)
#define KS23    13     // k-steps layers 2,3 (K=101 pad 104)

// ---- smem layout (float offsets) ----
#define F_BP1   0
#define F_BP2   (F_BP1 + KS1*NT12*32*4)        //  6656
#define F_BP3   (F_BP2 + KS23*NT12*32*4)       // 28288
#define F_AS1   (F_BP3 + KS23*NT3*32*4)        // 34944  (also chol staging 128*36)
#define F_AS2   (F_AS1 + TILE_M*KP1)           // 39552
#define F_MEAN  (F_AS2 + TILE_M*KP2)           // 53376
#define F_TOTAL (F_MEAN + TILE_M*ACT)          // 54144 floats = 216576 B

__constant__ int c_pos[21]   = {0,6,7,12,13,14,18,19,20,21,24,25,26,27,28,30,31,32,33,34,35};
__constant__ int c_upper[15] = {1,2,3,4,5,8,9,10,11,15,16,17,22,23,29};

// staging-time split (rounded)
__device__ __forceinline__ void tf32s(float x, uint32_t& hi, uint32_t& lo) {
    asm("cvt.rna.tf32.f32 %0, %1;" : "=r"(hi) : "f"(x));
    float r = x - __uint_as_float(hi);
    asm("cvt.rna.tf32.f32 %0, %1;" : "=r"(lo) : "f"(r));
}
// hot-loop split (truncation): hi = x with low 13 mantissa bits masked, lo = exact残
__device__ __forceinline__ void fsplit(float x, uint32_t& hi, uint32_t& lo) {
    uint32_t xb = __float_as_uint(x);
    hi = xb & 0xffffe000u;
    lo = __float_as_uint(x - __uint_as_float(hi));
}

__device__ __forceinline__ void mma8(float* c, const uint32_t* a, uint32_t b0, uint32_t b1) {
    asm volatile("mma.sync.aligned.m16n8k8.row.col.f32.tf32.tf32.f32 "
                 "{%0,%1,%2,%3},{%4,%5,%6,%7},{%8,%9},{%0,%1,%2,%3};"
                 : "+f"(c[0]), "+f"(c[1]), "+f"(c[2]), "+f"(c[3])
                 : "r"(a[0]), "r"(a[1]), "r"(a[2]), "r"(a[3]), "r"(b0), "r"(b1));
}

extern __shared__ float smem[];

// Warp GEMM, 3xTF32, term-major. Rows [wrow, wrow+16*MT), n-tiles [nt0, nt0+cnt).
template<int KS, int MT, int NTW, int KP>
__device__ __forceinline__ void wgemm(const float* __restrict__ As,
                                      const float4* __restrict__ Bp,
                                      int NTT, int nt0, int cnt,
                                      int wrow, int g, int t, int lane,
                                      float (&c)[MT][NTW][4])
{
    #pragma unroll
    for (int mt = 0; mt < MT; mt++)
        #pragma unroll
        for (int j = 0; j < NTW; j++)
            #pragma unroll
            for (int i = 0; i < 4; i++) c[mt][j][i] = 0.0f;

    #pragma unroll 1
    for (int ks = 0; ks < KS; ks++) {
        const int col = t + 8 * ks;

        // B fragments for this warp's n-tiles
        float4 bfr[NTW];
        #pragma unroll
        for (int j = 0; j < NTW; j++)
            if (j < cnt) bfr[j] = Bp[(ks * NTT + nt0 + j) * 32 + lane];

        // A fragments + cheap split
        uint32_t ahi[MT][4], alo[MT][4];
        #pragma unroll
        for (int mt = 0; mt < MT; mt++) {
            const float* r = As + (wrow + 16 * mt + g) * KP;
            fsplit(r[col],            ahi[mt][0], alo[mt][0]);
            fsplit(r[8 * KP + col],   ahi[mt][1], alo[mt][1]);
            fsplit(r[col + 4],        ahi[mt][2], alo[mt][2]);
            fsplit(r[8 * KP + col+4], ahi[mt][3], alo[mt][3]);
        }

        // term-major: same-accumulator reuse distance = MT*cnt
        #pragma unroll
        for (int term = 0; term < 3; term++)
            #pragma unroll
            for (int j = 0; j < NTW; j++) {
                if (j >= cnt) continue;
                uint32_t b0 = (term == 2) ? __float_as_uint(bfr[j].z) : __float_as_uint(bfr[j].x);
                uint32_t b1 = (term == 2) ? __float_as_uint(bfr[j].w) : __float_as_uint(bfr[j].y);
                #pragma unroll
                for (int mt = 0; mt < MT; mt++)
                    mma8(c[mt][j], (term == 1) ? alo[mt] : ahi[mt], b0, b1);
            }
    }
}

// relu + store C frags into As2 (cols < 100 only)
template<int MT, int NTW>
__device__ __forceinline__ void epi_relu(float (&c)[MT][NTW][4], float* As2,
                                         int wrow, int nt0, int cnt, int g, int t)
{
    #pragma unroll
    for (int mt = 0; mt < MT; mt++) {
        const int row = wrow + 16 * mt + g;
        #pragma unroll
        for (int j = 0; j < NTW; j++) {
            if (j >= cnt) continue;
            const int nt = nt0 + j;
            if (nt == 12 && t >= 2) continue;        // cols >= 100
            const int col = 8 * nt + 2 * t;
            float2 v0, v1;
            v0.x = fmaxf(c[mt][j][0], 0.f); v0.y = fmaxf(c[mt][j][1], 0.f);
            v1.x = fmaxf(c[mt][j][2], 0.f); v1.y = fmaxf(c[mt][j][3], 0.f);
            *reinterpret_cast<float2*>(As2 + row * KP2 + col)       = v0;
            *reinterpret_cast<float2*>(As2 + (row + 8) * KP2 + col) = v1;
        }
    }
}

__global__ void __launch_bounds__(TPB, 1)
actor_mma(const float* __restrict__ states,
          const float* __restrict__ W1, const float* __restrict__ b1,
          const float* __restrict__ W2, const float* __restrict__ b2,
          const float* __restrict__ Wm, const float* __restrict__ bm,
          const float* __restrict__ Wc, const float* __restrict__ bc,
          float* __restrict__ out, int B)
{
    const int tid  = threadIdx.x;
    const int lane = tid & 31;
    const int wid  = tid >> 5;
    const int g    = lane >> 2;
    const int t    = lane & 3;

    // layers 1,2: M2 x N4 split
    const int mh   = wid & 1;            // 64-row half
    const int nh   = wid >> 1;           // 0..3 n-group
    const int wrow = mh * 64;
    const int nt0  = (nh == 0) ? 0 : (1 + 3 * nh);   // {0,4,7,10}
    const int ncnt = (nh == 0) ? 4 : 3;
    // head gemm: M4 x N2 split
    const int mh3   = wid & 3;
    const int nh3   = wid >> 2;
    const int wrow3 = mh3 * 32;

    float* As1   = smem + F_AS1;
    float* As2   = smem + F_AS2;
    float* sMean = smem + F_MEAN;
    const float4* Bp1 = reinterpret_cast<const float4*>(smem + F_BP1);
    const float4* Bp2 = reinterpret_cast<const float4*>(smem + F_BP2);
    const float4* Bp3 = reinterpret_cast<const float4*>(smem + F_BP3);

    // ---- stage packed weight fragments (hi/lo tf32 split), biases folded ----
    for (int i = tid; i < KS1 * NT12 * 32; i += TPB) {
        int ln = i & 31, slot = i >> 5, ks = slot / NT12, nt = slot - ks * NT12;
        int gg = ln >> 2, tt = ln & 3, n = gg + 8 * nt, k0 = tt + 8 * ks, k1 = k0 + 4;
        float w0 = (n < L1D) ? (k0 < STATE ? W1[n * STATE + k0] : (k0 == STATE ? b1[n] : 0.f)) : 0.f;
        float w1 = (n < L1D) ? (k1 < STATE ? W1[n * STATE + k1] : (k1 == STATE ? b1[n] : 0.f)) : 0.f;
        uint32_t h0, l0, h1, l1; tf32s(w0, h0, l0); tf32s(w1, h1, l1);
        reinterpret_cast<uint4*>(smem + F_BP1)[i] = make_uint4(h0, h1, l0, l1);
    }
    for (int i = tid; i < KS23 * NT12 * 32; i += TPB) {
        int ln = i & 31, slot = i >> 5, ks = slot / NT12, nt = slot - ks * NT12;
        int gg = ln >> 2, tt = ln & 3, n = gg + 8 * nt, k0 = tt + 8 * ks, k1 = k0 + 4;
        float w0 = (n < L2D) ? (k0 < L1D ? W2[n * L1D + k0] : (k0 == L1D ? b2[n] : 0.f)) : 0.f;
        float w1 = (n < L2D) ? (k1 < L1D ? W2[n * L1D + k1] : (k1 == L1D ? b2[n] : 0.f)) : 0.f;
        uint32_t h0, l0, h1, l1; tf32s(w0, h0, l0); tf32s(w1, h1, l1);
        reinterpret_cast<uint4*>(smem + F_BP2)[i] = make_uint4(h0, h1, l0, l1);
    }
    for (int i = tid; i < KS23 * NT3 * 32; i += TPB) {
        int ln = i & 31, slot = i >> 5, ks = slot / NT3, nt = slot - ks * NT3;
        int gg = ln >> 2, tt = ln & 3, n = gg + 8 * nt, k0 = tt + 8 * ks, k1 = k0 + 4;
        float w0 = 0.f, w1 = 0.f;
        if (n < ACT) {
            w0 = k0 < L2D ? Wm[n * L2D + k0] : (k0 == L2D ? bm[n] : 0.f);
            w1 = k1 < L2D ? Wm[n * L2D + k1] : (k1 == L2D ? bm[n] : 0.f);
        } else if (n < NHEAD) {
            w0 = k0 < L2D ? Wc[(n - ACT) * L2D + k0] : (k0 == L2D ? bc[n - ACT] : 0.f);
            w1 = k1 < L2D ? Wc[(n - ACT) * L2D + k1] : (k1 == L2D ? bc[n - ACT] : 0.f);
        }
        uint32_t h0, l0, h1, l1; tf32s(w0, h0, l0); tf32s(w1, h1, l1);
        reinterpret_cast<uint4*>(smem + F_BP3)[i] = make_uint4(h0, h1, l0, l1);
    }
    for (int i = tid; i < TILE_M * KP2; i += TPB) As2[i] = 0.0f;
    __syncthreads();

    const int ntiles = (B + TILE_M - 1) / TILE_M;

    for (int tile = blockIdx.x; tile < ntiles; tile += gridDim.x) {
        // ---- load X rows (tid<128 -> row), pad cols 24..35: bias=1 then 0 ----
        if (tid < TILE_M) {
            long m = (long)tile * TILE_M + tid; if (m >= B) m = B - 1;
            const float4* src = reinterpret_cast<const float4*>(states + m * STATE);
            float4* dst = reinterpret_cast<float4*>(As1 + tid * KP1);
            #pragma unroll
            for (int q = 0; q < 6; q++) dst[q] = src[q];
            dst[6] = make_float4(1.f, 0.f, 0.f, 0.f);
            dst[7] = make_float4(0.f, 0.f, 0.f, 0.f);
            dst[8] = make_float4(0.f, 0.f, 0.f, 0.f);
        }
        __syncthreads();                                   // S1

        // ---- layer 1 (reads As1, writes As2) ----
        {
            float c1[4][4][4];
            wgemm<KS1, 4, 4, KP1>(As1, Bp1, NT12, nt0, ncnt, wrow, g, t, lane, c1);
            epi_relu<4, 4>(c1, As2, wrow, nt0, ncnt, g, t);
            if (tid < TILE_M) As2[tid * KP2 + 100] = 1.0f;
        }
        __syncthreads();                                   // S2

        // ---- layer 2 (reads + rewrites As2) ----
        {
            float c2[4][4][4];
            wgemm<KS23, 4, 4, KP2>(As2, Bp2, NT12, nt0, ncnt, wrow, g, t, lane, c2);
            __syncthreads();                               // S3: all reads done
            epi_relu<4, 4>(c2, As2, wrow, nt0, ncnt, g, t);
            if (tid < TILE_M) As2[tid * KP2 + 100] = 1.0f;
        }
        __syncthreads();                                   // S4

        // ---- head gemm + activation scatter ----
        {
            float c3[4][2][4];
            wgemm<KS23, 2, 2, KP2>(As2, Bp3, NT3, 2 * nh3, 2, wrow3, g, t, lane,
                                   *reinterpret_cast<float(*)[2][2][4]>(&c3[0]));
            float (&cc)[2][2][4] = *reinterpret_cast<float(*)[2][2][4]>(&c3[0]);
            #pragma unroll
            for (int mt = 0; mt < 2; mt++)
                #pragma unroll
                for (int j = 0; j < 2; j++)
                    #pragma unroll
                    for (int i = 0; i < 4; i++) {
                        int row = wrow3 + 16 * mt + g + ((i >= 2) ? 8 : 0);
                        int col = 8 * (2 * nh3 + j) + 2 * t + (i & 1);
                        float v = cc[mt][j][i];
                        if (col < ACT) {
                            sMean[row * ACT + col] = tanhf(v);
                        } else if (col < NHEAD) {
                            float sp = fmaxf(v, 0.f) + log1pf(expf(-fabsf(v)));
                            As1[row * 36 + c_pos[col - ACT]] = sp;
                        }
                    }
            if (tid < TILE_M) {
                #pragma unroll
                for (int j = 0; j < 15; j++) As1[tid * 36 + c_upper[j]] = 0.0f;
            }
        }
        __syncthreads();                                   // S5

        // ---- coalesced writeback ----
        if ((tile + 1) * TILE_M <= B) {
            float4* pm = reinterpret_cast<float4*>(out + (size_t)tile * (TILE_M * ACT));
            const float4* sm4 = reinterpret_cast<const float4*>(sMean);
            for (int i = tid; i < TILE_M * ACT / 4; i += TPB) pm[i] = sm4[i];
            float4* pc = reinterpret_cast<float4*>(out + (size_t)B * ACT + (size_t)tile * (TILE_M * 36));
            const float4* sc4 = reinterpret_cast<const float4*>(As1);
            for (int i = tid; i < TILE_M * 36 / 4; i += TPB) pc[i] = sc4[i];
        } else {
            int nrow = B - tile * TILE_M;
            for (int i = tid; i < nrow * ACT; i += TPB)
                out[(size_t)tile * (TILE_M * ACT) + i] = sMean[i];
            for (int i = tid; i < nrow * 36; i += TPB)
                out[(size_t)B * ACT + (size_t)tile * (TILE_M * 36) + i] = As1[i];
        }
        __syncthreads();                                   // S6
    }
}

extern "C" void kernel_launch(void* const* d_in, const int* in_sizes, int n_in,
                              void* d_out, int out_size)
{
    const float* states = (const float*)d_in[0];
    const float* W1 = (const float*)d_in[1];
    const float* b1 = (const float*)d_in[2];
    const float* W2 = (const float*)d_in[3];
    const float* b2 = (const float*)d_in[4];
    const float* Wm = (const float*)d_in[5];
    const float* bm = (const float*)d_in[6];
    const float* Wc = (const float*)d_in[7];
    const float* bc = (const float*)d_in[8];
    float* out = (float*)d_out;

    const int B = in_sizes[0] / STATE;
    const int ntiles = (B + TILE_M - 1) / TILE_M;
    const size_t smem_bytes = (size_t)F_TOTAL * sizeof(float);   // ~211.5 KB

    cudaFuncSetAttribute(actor_mma,
                         cudaFuncAttributeMaxDynamicSharedMemorySize,
                         (int)smem_bytes);

    int grid = ntiles < 148 ? ntiles : 148;
    actor_mma<<<grid, TPB, smem_bytes>>>(states, W1, b1, W2, b2,
                                         Wm, bm, Wc, bc, out, B);
}

// round 5
// speedup vs baseline: 2.1692x; 1.3742x over previous
#include <cuda_runtime.h>
#include <cuda_fp16.h>
#include <cstdint>

#define TPB     512
#define TILE_M  128
#define STATE   24
#define L1D     100
#define L2D     100
#define NHEAD   27
#define ACT     6

#define NT12    13     // n-tiles (104 cols) layers 1,2
#define NT3     4      // n-tiles (32 cols) head layer
#define KS1     2      // k16-steps layer1 (K=25 pad 32)
#define KS23    7      // k16-steps layers 2,3 (K=101 pad 112)

// activation planes: b32 words hold f16x2 (k-pair). row stride % 32 == 4 -> conflict-free
#define S1_32   36     // As1: hi pairs [0..15], lo at +16, pad 4
#define LO1     16
#define S2_32   116    // As2: hi pairs [0..55], lo at +56, pad 4
#define LO2     56

// ---- smem layout (b32 offsets) ----
#define F_BP1   0
#define F_BP2   (F_BP1 + KS1*NT12*32*4)        //  3328
#define F_BP3   (F_BP2 + KS23*NT12*32*4)       // 14976
#define F_AS1   (F_BP3 + KS23*NT3*32*4)        // 18560  (also chol fp32 staging 128*36)
#define F_AS2   (F_AS1 + TILE_M*S1_32)         // 23168
#define F_MEAN  (F_AS2 + TILE_M*S2_32)         // 38016
#define F_TOTAL (F_MEAN + TILE_M*ACT)          // 38784 b32 = 155136 B

__constant__ int c_pos[21]   = {0,6,7,12,13,14,18,19,20,21,24,25,26,27,28,30,31,32,33,34,35};
__constant__ int c_upper[15] = {1,2,3,4,5,8,9,10,11,15,16,17,22,23,29};

__device__ __forceinline__ uint32_t packh(__half a, __half b) {
    return (uint32_t)__half_as_ushort(a) | ((uint32_t)__half_as_ushort(b) << 16);
}
// hi/lo f16 split of two floats -> two packed b32 words
__device__ __forceinline__ void split2(float v0, float v1, uint32_t& hi, uint32_t& lo) {
    __half h0 = __float2half_rn(v0), h1 = __float2half_rn(v1);
    __half l0 = __float2half_rn(v0 - __half2float(h0));
    __half l1 = __float2half_rn(v1 - __half2float(h1));
    hi = packh(h0, h1); lo = packh(l0, l1);
}

__device__ __forceinline__ void mma16(float* c, const uint32_t* a, uint32_t b0, uint32_t b1) {
    asm volatile("mma.sync.aligned.m16n8k16.row.col.f32.f16.f16.f32 "
                 "{%0,%1,%2,%3},{%4,%5,%6,%7},{%8,%9},{%0,%1,%2,%3};"
                 : "+f"(c[0]), "+f"(c[1]), "+f"(c[2]), "+f"(c[3])
                 : "r"(a[0]), "r"(a[1]), "r"(a[2]), "r"(a[3]), "r"(b0), "r"(b1));
}

extern __shared__ uint32_t smem[];

// Warp GEMM over f16 hi/lo planes, term-major.
template<int KS, int MT, int NTW>
__device__ __forceinline__ void wgemm16(const uint32_t* __restrict__ A32, int S32, int LO,
                                        const uint4* __restrict__ Bp,
                                        int NTT, int nt0, int cnt,
                                        int wrow, int g, int t, int lane,
                                        float (&c)[MT][NTW][4])
{
    #pragma unroll
    for (int mt = 0; mt < MT; mt++)
        #pragma unroll
        for (int j = 0; j < NTW; j++)
            #pragma unroll
            for (int i = 0; i < 4; i++) c[mt][j][i] = 0.0f;

    #pragma unroll 1
    for (int ks = 0; ks < KS; ks++) {
        const int kb = ks * 8 + t;

        uint4 bfr[NTW];
        #pragma unroll
        for (int j = 0; j < NTW; j++)
            if (j < cnt) bfr[j] = Bp[(ks * NTT + nt0 + j) * 32 + lane];

        uint32_t ah[MT][4], al[MT][4];
        #pragma unroll
        for (int mt = 0; mt < MT; mt++) {
            const uint32_t* r0 = A32 + (wrow + 16 * mt + g) * S32;
            const uint32_t* r1 = r0 + 8 * S32;
            ah[mt][0] = r0[kb];          ah[mt][1] = r1[kb];
            ah[mt][2] = r0[kb + 4];      ah[mt][3] = r1[kb + 4];
            al[mt][0] = r0[kb + LO];     al[mt][1] = r1[kb + LO];
            al[mt][2] = r0[kb + LO + 4]; al[mt][3] = r1[kb + LO + 4];
        }

        #pragma unroll
        for (int term = 0; term < 3; term++)
            #pragma unroll
            for (int j = 0; j < NTW; j++) {
                if (j >= cnt) continue;
                uint32_t b0 = (term == 2) ? bfr[j].z : bfr[j].x;
                uint32_t b1 = (term == 2) ? bfr[j].w : bfr[j].y;
                #pragma unroll
                for (int mt = 0; mt < MT; mt++)
                    mma16(c[mt][j], (term == 1) ? al[mt] : ah[mt], b0, b1);
            }
    }
}

// relu + hi/lo split + store into As2 planes (cols < 100 only)
template<int MT, int NTW>
__device__ __forceinline__ void epi_relu16(float (&c)[MT][NTW][4], uint32_t* A2,
                                           int wrow, int nt0, int cnt, int g, int t)
{
    #pragma unroll
    for (int mt = 0; mt < MT; mt++) {
        const int row = wrow + 16 * mt + g;
        #pragma unroll
        for (int j = 0; j < NTW; j++) {
            if (j >= cnt) continue;
            const int nt = nt0 + j;
            if (nt == 12 && t >= 2) continue;      // cols >= 100
            const int pi = 4 * nt + t;             // k-pair index = col/2
            uint32_t h, l;
            split2(fmaxf(c[mt][j][0], 0.f), fmaxf(c[mt][j][1], 0.f), h, l);
            A2[row * S2_32 + pi] = h;  A2[row * S2_32 + LO2 + pi] = l;
            split2(fmaxf(c[mt][j][2], 0.f), fmaxf(c[mt][j][3], 0.f), h, l);
            A2[(row + 8) * S2_32 + pi] = h;  A2[(row + 8) * S2_32 + LO2 + pi] = l;
        }
    }
}

__global__ void __launch_bounds__(TPB, 1)
actor_mma(const float* __restrict__ states,
          const float* __restrict__ W1, const float* __restrict__ b1,
          const float* __restrict__ W2, const float* __restrict__ b2,
          const float* __restrict__ Wm, const float* __restrict__ bm,
          const float* __restrict__ Wc, const float* __restrict__ bc,
          float* __restrict__ out, int B)
{
    const int tid  = threadIdx.x;
    const int lane = tid & 31;
    const int wid  = tid >> 5;
    const int g    = lane >> 2;
    const int t    = lane & 3;

    // layers 1,2: M4 x N4
    const int wrow = (wid & 3) * 32;
    const int nh   = wid >> 2;
    const int nt0  = (nh == 0) ? 0 : (1 + 3 * nh);   // {0,4,7,10}
    const int ncnt = (nh == 0) ? 4 : 3;
    // head gemm: M8 x N2
    const int wrow3 = (wid & 7) * 16;
    const int nt03  = (wid >> 3) * 2;

    uint32_t* As1 = smem + F_AS1;
    uint32_t* As2 = smem + F_AS2;
    float* sMean  = reinterpret_cast<float*>(smem + F_MEAN);
    float* sChol  = reinterpret_cast<float*>(smem + F_AS1);   // overlay (both 128*36 b32)
    const uint4* Bp1 = reinterpret_cast<const uint4*>(smem + F_BP1);
    const uint4* Bp2 = reinterpret_cast<const uint4*>(smem + F_BP2);
    const uint4* Bp3 = reinterpret_cast<const uint4*>(smem + F_BP3);

    // ---- stage packed f16 hi/lo weight fragments, biases folded as K-column ----
    // frag layout per (ks,nt,lane): n = (lane>>2)+8nt, k0 = 16ks+2t
    // uint4 = { hi(k0,k0+1), hi(k0+8,k0+9), lo(k0,k0+1), lo(k0+8,k0+9) }
    for (int i = tid; i < KS1 * NT12 * 32; i += TPB) {
        int ln = i & 31, slot = i >> 5, ks = slot / NT12, nt = slot - ks * NT12;
        int n = (ln >> 2) + 8 * nt, k0 = 16 * ks + 2 * (ln & 3);
        float w[4];
        #pragma unroll
        for (int q = 0; q < 4; q++) {
            int k = k0 + (q >> 1) * 8 + (q & 1);
            w[q] = (n < L1D) ? (k < STATE ? W1[n * STATE + k] : (k == STATE ? b1[n] : 0.f)) : 0.f;
        }
        uint4 fr; uint32_t lo0, lo1;
        split2(w[0], w[1], fr.x, lo0); split2(w[2], w[3], fr.y, lo1);
        fr.z = lo0; fr.w = lo1;
        reinterpret_cast<uint4*>(smem + F_BP1)[i] = fr;
    }
    for (int i = tid; i < KS23 * NT12 * 32; i += TPB) {
        int ln = i & 31, slot = i >> 5, ks = slot / NT12, nt = slot - ks * NT12;
        int n = (ln >> 2) + 8 * nt, k0 = 16 * ks + 2 * (ln & 3);
        float w[4];
        #pragma unroll
        for (int q = 0; q < 4; q++) {
            int k = k0 + (q >> 1) * 8 + (q & 1);
            w[q] = (n < L2D) ? (k < L1D ? W2[n * L1D + k] : (k == L1D ? b2[n] : 0.f)) : 0.f;
        }
        uint4 fr; uint32_t lo0, lo1;
        split2(w[0], w[1], fr.x, lo0); split2(w[2], w[3], fr.y, lo1);
        fr.z = lo0; fr.w = lo1;
        reinterpret_cast<uint4*>(smem + F_BP2)[i] = fr;
    }
    for (int i = tid; i < KS23 * NT3 * 32; i += TPB) {
        int ln = i & 31, slot = i >> 5, ks = slot / NT3, nt = slot - ks * NT3;
        int n = (ln >> 2) + 8 * nt, k0 = 16 * ks + 2 * (ln & 3);
        float w[4];
        #pragma unroll
        for (int q = 0; q < 4; q++) {
            int k = k0 + (q >> 1) * 8 + (q & 1);
            float v = 0.f;
            if (n < ACT)        v = k < L2D ? Wm[n * L2D + k] : (k == L2D ? bm[n] : 0.f);
            else if (n < NHEAD) v = k < L2D ? Wc[(n - ACT) * L2D + k] : (k == L2D ? bc[n - ACT] : 0.f);
            w[q] = v;
        }
        uint4 fr; uint32_t lo0, lo1;
        split2(w[0], w[1], fr.x, lo0); split2(w[2], w[3], fr.y, lo1);
        fr.z = lo0; fr.w = lo1;
        reinterpret_cast<uint4*>(smem + F_BP3)[i] = fr;
    }
    // As2 pad pairs 50..55 (cols 100..111): bias col 100 = 1, rest 0; epi never touches
    if (tid < TILE_M) {
        As2[tid * S2_32 + 50]       = packh(__float2half_rn(1.f), __ushort_as_half(0));
        As2[tid * S2_32 + LO2 + 50] = 0u;
        #pragma unroll
        for (int p = 51; p < 56; p++) {
            As2[tid * S2_32 + p] = 0u;
            As2[tid * S2_32 + LO2 + p] = 0u;
        }
    }
    __syncthreads();

    const int ntiles = (B + TILE_M - 1) / TILE_M;

    for (int tile = blockIdx.x; tile < ntiles; tile += gridDim.x) {
        // ---- load X rows -> f16 hi/lo planes; pairs 12=bias(1,0), 13..15=0 ----
        if (tid < TILE_M) {
            long m = (long)tile * TILE_M + tid; if (m >= B) m = B - 1;
            const float4* src = reinterpret_cast<const float4*>(states + m * STATE);
            uint32_t* rh = As1 + tid * S1_32;
            #pragma unroll
            for (int q = 0; q < 6; q++) {
                float4 v = src[q];
                uint32_t h, l;
                split2(v.x, v.y, h, l);
                rh[2 * q] = h; rh[LO1 + 2 * q] = l;
                split2(v.z, v.w, h, l);
                rh[2 * q + 1] = h; rh[LO1 + 2 * q + 1] = l;
            }
            rh[12] = packh(__float2half_rn(1.f), __ushort_as_half(0));
            rh[LO1 + 12] = 0u;
            #pragma unroll
            for (int p = 13; p < 16; p++) { rh[p] = 0u; rh[LO1 + p] = 0u; }
        }
        __syncthreads();                                   // S1

        // ---- layer 1 ----
        {
            float c1[2][4][4];
            wgemm16<KS1, 2, 4>(As1, S1_32, LO1, Bp1, NT12, nt0, ncnt, wrow, g, t, lane, c1);
            epi_relu16<2, 4>(c1, As2, wrow, nt0, ncnt, g, t);
        }
        __syncthreads();                                   // S2

        // ---- layer 2 ----
        {
            float c2[2][4][4];
            wgemm16<KS23, 2, 4>(As2, S2_32, LO2, Bp2, NT12, nt0, ncnt, wrow, g, t, lane, c2);
            __syncthreads();                               // S3: reads done
            epi_relu16<2, 4>(c2, As2, wrow, nt0, ncnt, g, t);
        }
        __syncthreads();                                   // S4

        // ---- head gemm + activation scatter ----
        {
            float c3[1][2][4];
            wgemm16<KS23, 1, 2>(As2, S2_32, LO2, Bp3, NT3, nt03, 2, wrow3, g, t, lane, c3);
            #pragma unroll
            for (int j = 0; j < 2; j++)
                #pragma unroll
                for (int i = 0; i < 4; i++) {
                    int row = wrow3 + g + ((i >= 2) ? 8 : 0);
                    int col = 8 * (nt03 + j) + 2 * t + (i & 1);
                    float v = c3[0][j][i];
                    if (col < ACT) {
                        sMean[row * ACT + col] = tanhf(v);
                    } else if (col < NHEAD) {
                        float sp = fmaxf(v, 0.f) + log1pf(expf(-fabsf(v)));
                        sChol[row * 36 + c_pos[col - ACT]] = sp;
                    }
                }
            if (tid < TILE_M) {
                #pragma unroll
                for (int j = 0; j < 15; j++) sChol[tid * 36 + c_upper[j]] = 0.0f;
            }
        }
        __syncthreads();                                   // S5

        // ---- coalesced writeback ----
        if ((tile + 1) * TILE_M <= B) {
            float4* pm = reinterpret_cast<float4*>(out + (size_t)tile * (TILE_M * ACT));
            const float4* sm4 = reinterpret_cast<const float4*>(sMean);
            for (int i = tid; i < TILE_M * ACT / 4; i += TPB) pm[i] = sm4[i];
            float4* pc = reinterpret_cast<float4*>(out + (size_t)B * ACT + (size_t)tile * (TILE_M * 36));
            const float4* sc4 = reinterpret_cast<const float4*>(sChol);
            for (int i = tid; i < TILE_M * 36 / 4; i += TPB) pc[i] = sc4[i];
        } else {
            int nrow = B - tile * TILE_M;
            for (int i = tid; i < nrow * ACT; i += TPB)
                out[(size_t)tile * (TILE_M * ACT) + i] = sMean[i];
            for (int i = tid; i < nrow * 36; i += TPB)
                out[(size_t)B * ACT + (size_t)tile * (TILE_M * 36) + i] = sChol[i];
        }
        __syncthreads();                                   // S6 (staging reuse)
    }
}

extern "C" void kernel_launch(void* const* d_in, const int* in_sizes, int n_in,
                              void* d_out, int out_size)
{
    const float* states = (const float*)d_in[0];
    const float* W1 = (const float*)d_in[1];
    const float* b1 = (const float*)d_in[2];
    const float* W2 = (const float*)d_in[3];
    const float* b2 = (const float*)d_in[4];
    const float* Wm = (const float*)d_in[5];
    const float* bm = (const float*)d_in[6];
    const float* Wc = (const float*)d_in[7];
    const float* bc = (const float*)d_in[8];
    float* out = (float*)d_out;

    const int B = in_sizes[0] / STATE;
    const int ntiles = (B + TILE_M - 1) / TILE_M;
    const size_t smem_bytes = (size_t)F_TOTAL * 4;   // ~155 KB

    cudaFuncSetAttribute(actor_mma,
                         cudaFuncAttributeMaxDynamicSharedMemorySize,
                         (int)smem_bytes);

    int grid = ntiles < 148 ? ntiles : 148;
    actor_mma<<<grid, TPB, smem_bytes>>>(states, W1, b1, W2, b2,
                                         Wm, bm, Wc, bc, out, B);
}